// round 1
// baseline (speedup 1.0000x reference)
#include <cuda_runtime.h>
#include <math.h>

#define NMAX 50000
#define KD 128

// ---- scratch (static device globals; no allocation allowed) ----
__device__ float g_h[(size_t)NMAX * KD];    // pool output h of current layer
__device__ float g_agg[(size_t)NMAX * KD];  // scatter-sum accumulator
__device__ float g_o0[(size_t)NMAX * KD];   // layer-0 output

// =====================================================================
// pool GEMM with fused row L2-normalization:
//   H[m,o] = relu( inv_norm[m] * sum_k X[m,k]*W[o,k] + B[o] )
// tile: 64 rows x 128 cols, K=128 fully in smem (k-major, padded)
// =====================================================================
__global__ __launch_bounds__(256, 2)
void pool_gemm(const float* __restrict__ X, const float* __restrict__ W,
               const float* __restrict__ B, float* __restrict__ H, int n)
{
    extern __shared__ float sm[];
    float* As   = sm;                 // [128][68]  k-major A tile
    float* Ws   = As + KD * 68;       // [128][132] k-major weights
    float* invn = Ws + KD * 132;      // [64]

    const int t = threadIdx.x;
    const int warp = t >> 5, lane = t & 31;
    const int m0 = blockIdx.x * 64;

    // load W transposed to k-major (coalesced global reads)
    for (int i = t; i < KD * KD; i += 256) {
        int o = i >> 7, k = i & 127;
        Ws[k * 132 + o] = W[i];
    }

    // load 64-row X tile; each (warp,i) owns one full row -> warp-reduce sumsq
    #pragma unroll
    for (int i = 0; i < 8; ++i) {
        int row = warp + 8 * i;
        int m = m0 + row;
        float4 v = make_float4(0.f, 0.f, 0.f, 0.f);
        if (m < n) v = reinterpret_cast<const float4*>(X)[(size_t)m * 32 + lane];
        float s = v.x * v.x + v.y * v.y + v.z * v.z + v.w * v.w;
        #pragma unroll
        for (int off = 16; off > 0; off >>= 1)
            s += __shfl_xor_sync(0xffffffffu, s, off);
        if (lane == 0) invn[row] = 1.0f / fmaxf(sqrtf(s), 1e-12f);
        int k = lane * 4;
        As[(k + 0) * 68 + row] = v.x;
        As[(k + 1) * 68 + row] = v.y;
        As[(k + 2) * 68 + row] = v.z;
        As[(k + 3) * 68 + row] = v.w;
    }
    __syncthreads();

    // warp 2D tiling: 8 warps = 4 (M) x 2 (N); lane = 4 (M) x 8 (N)
    const int wr = warp & 3, wc = warp >> 2;
    const int lr = lane >> 3, lc = lane & 7;
    const int mrow = wr * 16 + lr * 4;     // 4 consecutive rows
    const int ocol = wc * 64 + lc * 8;     // 8 consecutive cols

    float acc[4][8];
    #pragma unroll
    for (int i = 0; i < 4; ++i)
        #pragma unroll
        for (int j = 0; j < 8; ++j) acc[i][j] = 0.f;

    #pragma unroll 8
    for (int k = 0; k < KD; ++k) {
        float4 av  = *reinterpret_cast<const float4*>(&As[k * 68 + mrow]);
        float4 b0v = *reinterpret_cast<const float4*>(&Ws[k * 132 + ocol]);
        float4 b1v = *reinterpret_cast<const float4*>(&Ws[k * 132 + ocol + 4]);
        float a[4] = {av.x, av.y, av.z, av.w};
        float b[8] = {b0v.x, b0v.y, b0v.z, b0v.w, b1v.x, b1v.y, b1v.z, b1v.w};
        #pragma unroll
        for (int i = 0; i < 4; ++i)
            #pragma unroll
            for (int j = 0; j < 8; ++j)
                acc[i][j] = fmaf(a[i], b[j], acc[i][j]);
    }

    float bs[8];
    #pragma unroll
    for (int j = 0; j < 8; ++j) bs[j] = B[ocol + j];

    #pragma unroll
    for (int i = 0; i < 4; ++i) {
        int m = m0 + mrow + i;
        if (m >= n) continue;
        float inv = invn[mrow + i];
        float4 r0, r1;
        r0.x = fmaxf(fmaf(acc[i][0], inv, bs[0]), 0.f);
        r0.y = fmaxf(fmaf(acc[i][1], inv, bs[1]), 0.f);
        r0.z = fmaxf(fmaf(acc[i][2], inv, bs[2]), 0.f);
        r0.w = fmaxf(fmaf(acc[i][3], inv, bs[3]), 0.f);
        r1.x = fmaxf(fmaf(acc[i][4], inv, bs[4]), 0.f);
        r1.y = fmaxf(fmaf(acc[i][5], inv, bs[5]), 0.f);
        r1.z = fmaxf(fmaf(acc[i][6], inv, bs[6]), 0.f);
        r1.w = fmaxf(fmaf(acc[i][7], inv, bs[7]), 0.f);
        reinterpret_cast<float4*>(H)[(size_t)m * 32 + (ocol >> 2)]     = r0;
        reinterpret_cast<float4*>(H)[(size_t)m * 32 + (ocol >> 2) + 1] = r1;
    }
}

// =====================================================================
// fused fc: OUT[m,o] = act( sum_k H[m,k]*W1[o,k] + sqrt(G[m,k])*W2[o,k]
//                           + B1[o] + B2[o] )
// =====================================================================
template <int FOUT, bool RELU>
__global__ __launch_bounds__(256, 1)
void fc_gemm(const float* __restrict__ Hin, const float* __restrict__ G,
             const float* __restrict__ W1, const float* __restrict__ W2,
             const float* __restrict__ B1, const float* __restrict__ B2,
             float* __restrict__ OUT, int n)
{
    constexpr int WROW = FOUT + 4;
    constexpr int TN = FOUT / 16;
    extern __shared__ float sm[];
    float* Ah  = sm;                      // [128][68]
    float* Ag  = Ah + KD * 68;            // [128][68]
    float* W1s = Ag + KD * 68;            // [128][WROW]
    float* W2s = W1s + KD * WROW;         // [128][WROW]

    const int t = threadIdx.x;
    const int warp = t >> 5, lane = t & 31;
    const int m0 = blockIdx.x * 64;

    for (int i = t; i < FOUT * KD; i += 256) {
        int o = i >> 7, k = i & 127;
        W1s[k * WROW + o] = W1[i];
        W2s[k * WROW + o] = W2[i];
    }

    #pragma unroll
    for (int i = 0; i < 8; ++i) {
        int row = warp + 8 * i;
        int m = m0 + row;
        float4 v = make_float4(0.f, 0.f, 0.f, 0.f);
        float4 g = make_float4(0.f, 0.f, 0.f, 0.f);
        if (m < n) {
            v = reinterpret_cast<const float4*>(Hin)[(size_t)m * 32 + lane];
            g = reinterpret_cast<const float4*>(G)[(size_t)m * 32 + lane];
        }
        g.x = sqrtf(g.x); g.y = sqrtf(g.y); g.z = sqrtf(g.z); g.w = sqrtf(g.w);
        int k = lane * 4;
        Ah[(k + 0) * 68 + row] = v.x;
        Ah[(k + 1) * 68 + row] = v.y;
        Ah[(k + 2) * 68 + row] = v.z;
        Ah[(k + 3) * 68 + row] = v.w;
        Ag[(k + 0) * 68 + row] = g.x;
        Ag[(k + 1) * 68 + row] = g.y;
        Ag[(k + 2) * 68 + row] = g.z;
        Ag[(k + 3) * 68 + row] = g.w;
    }
    __syncthreads();

    const int wr = warp & 3, wc = warp >> 2;
    const int lr = lane >> 3, lc = lane & 7;
    const int mrow = wr * 16 + lr * 4;
    const int ocol = wc * (FOUT / 2) + lc * TN;

    float acc[4][TN];
    #pragma unroll
    for (int i = 0; i < 4; ++i)
        #pragma unroll
        for (int j = 0; j < TN; ++j) acc[i][j] = 0.f;

    #pragma unroll 4
    for (int k = 0; k < KD; ++k) {
        float4 ahv = *reinterpret_cast<const float4*>(&Ah[k * 68 + mrow]);
        float4 agv = *reinterpret_cast<const float4*>(&Ag[k * 68 + mrow]);
        float ah[4] = {ahv.x, ahv.y, ahv.z, ahv.w};
        float ag[4] = {agv.x, agv.y, agv.z, agv.w};
        float b1r[TN], b2r[TN];
        #pragma unroll
        for (int j4 = 0; j4 < TN / 4; ++j4) {
            float4 w1v = *reinterpret_cast<const float4*>(&W1s[k * WROW + ocol + 4 * j4]);
            float4 w2v = *reinterpret_cast<const float4*>(&W2s[k * WROW + ocol + 4 * j4]);
            b1r[4 * j4 + 0] = w1v.x; b1r[4 * j4 + 1] = w1v.y;
            b1r[4 * j4 + 2] = w1v.z; b1r[4 * j4 + 3] = w1v.w;
            b2r[4 * j4 + 0] = w2v.x; b2r[4 * j4 + 1] = w2v.y;
            b2r[4 * j4 + 2] = w2v.z; b2r[4 * j4 + 3] = w2v.w;
        }
        #pragma unroll
        for (int i = 0; i < 4; ++i)
            #pragma unroll
            for (int j = 0; j < TN; ++j)
                acc[i][j] = fmaf(ah[i], b1r[j], fmaf(ag[i], b2r[j], acc[i][j]));
    }

    float bs[TN];
    #pragma unroll
    for (int j = 0; j < TN; ++j) bs[j] = B1[ocol + j] + B2[ocol + j];

    #pragma unroll
    for (int i = 0; i < 4; ++i) {
        int m = m0 + mrow + i;
        if (m >= n) continue;
        #pragma unroll
        for (int j4 = 0; j4 < TN / 4; ++j4) {
            float4 r;
            r.x = acc[i][4 * j4 + 0] + bs[4 * j4 + 0];
            r.y = acc[i][4 * j4 + 1] + bs[4 * j4 + 1];
            r.z = acc[i][4 * j4 + 2] + bs[4 * j4 + 2];
            r.w = acc[i][4 * j4 + 3] + bs[4 * j4 + 3];
            if (RELU) {
                r.x = fmaxf(r.x, 0.f); r.y = fmaxf(r.y, 0.f);
                r.z = fmaxf(r.z, 0.f); r.w = fmaxf(r.w, 0.f);
            }
            reinterpret_cast<float4*>(OUT)[(size_t)m * (FOUT / 4) + (ocol >> 2) + j4] = r;
        }
    }
}

// =====================================================================
// SpMM scatter: AGG[dst,:] += val * H[src,:]^2   (one warp per edge,
// vector f32x4 reduction atomics -> 4x fewer LTS atomic ops)
// =====================================================================
__global__ __launch_bounds__(256)
void spmm_kernel(const int* __restrict__ src, const int* __restrict__ dst,
                 const float* __restrict__ val, const float* __restrict__ Hm,
                 float* __restrict__ AGG, int E)
{
    int gw = (int)((blockIdx.x * 256u + threadIdx.x) >> 5);
    int lane = threadIdx.x & 31;
    if (gw >= E) return;
    int s = src[gw];
    int d = dst[gw];
    float v = val[gw];
    float4 h = reinterpret_cast<const float4*>(Hm)[(size_t)s * 32 + lane];
    float4 r;
    r.x = h.x * h.x * v;
    r.y = h.y * h.y * v;
    r.z = h.z * h.z * v;
    r.w = h.w * h.w * v;
    float* p = AGG + (size_t)d * 128 + lane * 4;
    asm volatile("red.global.add.v4.f32 [%0], {%1, %2, %3, %4};"
                 :: "l"(p), "f"(r.x), "f"(r.y), "f"(r.z), "f"(r.w) : "memory");
}

__global__ void zero_kernel(float4* __restrict__ p, int n4)
{
    int i = blockIdx.x * blockDim.x + threadIdx.x;
    int stride = gridDim.x * blockDim.x;
    float4 z = make_float4(0.f, 0.f, 0.f, 0.f);
    for (; i < n4; i += stride) p[i] = z;
}

// =====================================================================
extern "C" void kernel_launch(void* const* d_in, const int* in_sizes, int n_in,
                              void* d_out, int out_size)
{
    const float* x     = (const float*)d_in[0];
    const int*   esrc  = (const int*)  d_in[1];
    const int*   edst  = (const int*)  d_in[2];
    const float* eval_ = (const float*)d_in[3];
    const float* pw0   = (const float*)d_in[4];
    const float* pb0   = (const float*)d_in[5];
    const float* f1w0  = (const float*)d_in[6];
    const float* f1b0  = (const float*)d_in[7];
    const float* f2w0  = (const float*)d_in[8];
    const float* f2b0  = (const float*)d_in[9];
    const float* pw1   = (const float*)d_in[10];
    const float* pb1   = (const float*)d_in[11];
    const float* f1w1  = (const float*)d_in[12];
    const float* f1b1  = (const float*)d_in[13];
    const float* f2w1  = (const float*)d_in[14];
    const float* f2b1  = (const float*)d_in[15];
    float* out = (float*)d_out;

    int n = in_sizes[0] / KD;
    int E = in_sizes[1];

    float *hP, *aP, *oP;
    cudaGetSymbolAddress((void**)&hP, g_h);
    cudaGetSymbolAddress((void**)&aP, g_agg);
    cudaGetSymbolAddress((void**)&oP, g_o0);

    const int POOL_SMEM  = (KD * 68 + KD * 132 + 64) * 4;   // 102,912 B
    const int FC128_SMEM = (2 * KD * 68 + 2 * KD * 132) * 4; // 204,800 B
    const int FC64_SMEM  = (4 * KD * 68) * 4;                // 139,264 B
    cudaFuncSetAttribute(pool_gemm,         cudaFuncAttributeMaxDynamicSharedMemorySize, POOL_SMEM);
    cudaFuncSetAttribute(fc_gemm<128, true>, cudaFuncAttributeMaxDynamicSharedMemorySize, FC128_SMEM);
    cudaFuncSetAttribute(fc_gemm<64, false>, cudaFuncAttributeMaxDynamicSharedMemorySize, FC64_SMEM);

    int mb = (n + 63) / 64;
    int sb = (int)(((long long)E * 32 + 255) / 256);

    // ---- layer 0 ----
    pool_gemm<<<mb, 256, POOL_SMEM>>>(x, pw0, pb0, hP, n);
    zero_kernel<<<2048, 256>>>((float4*)aP, n * 32);
    spmm_kernel<<<sb, 256>>>(esrc, edst, eval_, hP, aP, E);
    fc_gemm<128, true><<<mb, 256, FC128_SMEM>>>(hP, aP, f1w0, f2w0, f1b0, f2b0, oP, n);

    // ---- layer 1 ----
    pool_gemm<<<mb, 256, POOL_SMEM>>>(oP, pw1, pb1, hP, n);
    zero_kernel<<<2048, 256>>>((float4*)aP, n * 32);
    spmm_kernel<<<sb, 256>>>(esrc, edst, eval_, hP, aP, E);
    fc_gemm<64, false><<<mb, 256, FC64_SMEM>>>(hP, aP, f1w1, f2w1, f1b1, f2b1, out, n);
}

// round 2
// speedup vs baseline: 1.1610x; 1.1610x over previous
#include <cuda_runtime.h>
#include <math.h>

#define NMAX 50000
#define KD 128

__device__ float g_h[(size_t)NMAX * KD];
__device__ float g_agg[(size_t)NMAX * KD];
__device__ float g_o0[(size_t)NMAX * KD];

// =====================================================================
// pool GEMM + fused row L2-norm:
//   H[m,o] = relu( inv_norm[m] * (X[m,:] . W[o,:]) + B[o] )
// tile 64 rows x 128 cols; conflict-free lane mapping:
//   thread cols = {c0..c0+3, c0+32..c0+35}, c0 = wc*64 + lc*4
// =====================================================================
__global__ __launch_bounds__(256, 2)
void pool_gemm(const float* __restrict__ X, const float* __restrict__ W,
               const float* __restrict__ B, float* __restrict__ H, int n)
{
    extern __shared__ float sm[];
    float* As   = sm;                 // [128 k][68 row]
    float* Ws   = As + KD * 68;       // [128 k][132 col]
    float* invn = Ws + KD * 132;      // [64]

    const int t = threadIdx.x;
    const int warp = t >> 5, lane = t & 31;
    const int m0 = blockIdx.x * 64;

    for (int i = t; i < KD * KD; i += 256) {
        int o = i >> 7, k = i & 127;
        Ws[k * 132 + o] = W[i];
    }

    #pragma unroll
    for (int i = 0; i < 8; ++i) {
        int row = warp + 8 * i;
        int m = m0 + row;
        float4 v = make_float4(0.f, 0.f, 0.f, 0.f);
        if (m < n) v = reinterpret_cast<const float4*>(X)[(size_t)m * 32 + lane];
        float s = v.x * v.x + v.y * v.y + v.z * v.z + v.w * v.w;
        #pragma unroll
        for (int off = 16; off > 0; off >>= 1)
            s += __shfl_xor_sync(0xffffffffu, s, off);
        if (lane == 0) invn[row] = 1.0f / fmaxf(sqrtf(s), 1e-12f);
        int k = lane * 4;
        As[(k + 0) * 68 + row] = v.x;
        As[(k + 1) * 68 + row] = v.y;
        As[(k + 2) * 68 + row] = v.z;
        As[(k + 3) * 68 + row] = v.w;
    }
    __syncthreads();

    const int wr = warp & 3, wc = warp >> 2;
    const int lr = lane >> 3, lc = lane & 7;
    const int mrow = wr * 16 + lr * 4;
    const int c0 = wc * 64 + lc * 4;       // strided col pair: c0, c0+32

    float acc[4][8];
    #pragma unroll
    for (int i = 0; i < 4; ++i)
        #pragma unroll
        for (int j = 0; j < 8; ++j) acc[i][j] = 0.f;

    #pragma unroll 8
    for (int k = 0; k < KD; ++k) {
        float4 av  = *reinterpret_cast<const float4*>(&As[k * 68 + mrow]);
        float4 b0v = *reinterpret_cast<const float4*>(&Ws[k * 132 + c0]);
        float4 b1v = *reinterpret_cast<const float4*>(&Ws[k * 132 + c0 + 32]);
        float a[4] = {av.x, av.y, av.z, av.w};
        float b[8] = {b0v.x, b0v.y, b0v.z, b0v.w, b1v.x, b1v.y, b1v.z, b1v.w};
        #pragma unroll
        for (int i = 0; i < 4; ++i)
            #pragma unroll
            for (int j = 0; j < 8; ++j)
                acc[i][j] = fmaf(a[i], b[j], acc[i][j]);
    }

    float bs[8];
    #pragma unroll
    for (int j = 0; j < 4; ++j) { bs[j] = B[c0 + j]; bs[j + 4] = B[c0 + 32 + j]; }

    #pragma unroll
    for (int i = 0; i < 4; ++i) {
        int m = m0 + mrow + i;
        if (m >= n) continue;
        float inv = invn[mrow + i];
        float4 r0, r1;
        r0.x = fmaxf(fmaf(acc[i][0], inv, bs[0]), 0.f);
        r0.y = fmaxf(fmaf(acc[i][1], inv, bs[1]), 0.f);
        r0.z = fmaxf(fmaf(acc[i][2], inv, bs[2]), 0.f);
        r0.w = fmaxf(fmaf(acc[i][3], inv, bs[3]), 0.f);
        r1.x = fmaxf(fmaf(acc[i][4], inv, bs[4]), 0.f);
        r1.y = fmaxf(fmaf(acc[i][5], inv, bs[5]), 0.f);
        r1.z = fmaxf(fmaf(acc[i][6], inv, bs[6]), 0.f);
        r1.w = fmaxf(fmaf(acc[i][7], inv, bs[7]), 0.f);
        reinterpret_cast<float4*>(H)[(size_t)m * 32 + (c0 >> 2)]     = r0;
        reinterpret_cast<float4*>(H)[(size_t)m * 32 + (c0 >> 2) + 8] = r1;
    }
}

// =====================================================================
// fused fc: OUT[m,o] = act( H.W1^T + sqrt(G).W2^T + B1 + B2 )
// NV = FOUT/64 float4-groups per thread at cols c0 + g*32
// =====================================================================
template <int FOUT, bool RELU>
__global__ __launch_bounds__(256, 1)
void fc_gemm(const float* __restrict__ Hin, const float* __restrict__ G,
             const float* __restrict__ W1, const float* __restrict__ W2,
             const float* __restrict__ B1, const float* __restrict__ B2,
             float* __restrict__ OUT, int n)
{
    constexpr int WROW = FOUT + 4;
    constexpr int NV = FOUT / 64;          // 2 for 128, 1 for 64
    extern __shared__ float sm[];
    float* Ah  = sm;                      // [128][68]
    float* Ag  = Ah + KD * 68;            // [128][68]
    float* W1s = Ag + KD * 68;            // [128][WROW]
    float* W2s = W1s + KD * WROW;

    const int t = threadIdx.x;
    const int warp = t >> 5, lane = t & 31;
    const int m0 = blockIdx.x * 64;

    for (int i = t; i < FOUT * KD; i += 256) {
        int o = i >> 7, k = i & 127;
        W1s[k * WROW + o] = W1[i];
        W2s[k * WROW + o] = W2[i];
    }

    #pragma unroll
    for (int i = 0; i < 8; ++i) {
        int row = warp + 8 * i;
        int m = m0 + row;
        float4 v = make_float4(0.f, 0.f, 0.f, 0.f);
        float4 g = make_float4(0.f, 0.f, 0.f, 0.f);
        if (m < n) {
            v = reinterpret_cast<const float4*>(Hin)[(size_t)m * 32 + lane];
            g = reinterpret_cast<const float4*>(G)[(size_t)m * 32 + lane];
        }
        g.x = sqrtf(g.x); g.y = sqrtf(g.y); g.z = sqrtf(g.z); g.w = sqrtf(g.w);
        int k = lane * 4;
        Ah[(k + 0) * 68 + row] = v.x;
        Ah[(k + 1) * 68 + row] = v.y;
        Ah[(k + 2) * 68 + row] = v.z;
        Ah[(k + 3) * 68 + row] = v.w;
        Ag[(k + 0) * 68 + row] = g.x;
        Ag[(k + 1) * 68 + row] = g.y;
        Ag[(k + 2) * 68 + row] = g.z;
        Ag[(k + 3) * 68 + row] = g.w;
    }
    __syncthreads();

    const int wr = warp & 3, wc = warp >> 2;
    const int lr = lane >> 3, lc = lane & 7;
    const int mrow = wr * 16 + lr * 4;
    const int c0 = wc * (FOUT / 2) + lc * 4;

    float acc[4][NV * 4];
    #pragma unroll
    for (int i = 0; i < 4; ++i)
        #pragma unroll
        for (int j = 0; j < NV * 4; ++j) acc[i][j] = 0.f;

    #pragma unroll 8
    for (int k = 0; k < KD; ++k) {
        float4 ahv = *reinterpret_cast<const float4*>(&Ah[k * 68 + mrow]);
        float4 agv = *reinterpret_cast<const float4*>(&Ag[k * 68 + mrow]);
        float ah[4] = {ahv.x, ahv.y, ahv.z, ahv.w};
        float ag[4] = {agv.x, agv.y, agv.z, agv.w};
        float b1r[NV * 4], b2r[NV * 4];
        #pragma unroll
        for (int g = 0; g < NV; ++g) {
            float4 w1v = *reinterpret_cast<const float4*>(&W1s[k * WROW + c0 + g * 32]);
            float4 w2v = *reinterpret_cast<const float4*>(&W2s[k * WROW + c0 + g * 32]);
            b1r[4*g+0] = w1v.x; b1r[4*g+1] = w1v.y; b1r[4*g+2] = w1v.z; b1r[4*g+3] = w1v.w;
            b2r[4*g+0] = w2v.x; b2r[4*g+1] = w2v.y; b2r[4*g+2] = w2v.z; b2r[4*g+3] = w2v.w;
        }
        #pragma unroll
        for (int i = 0; i < 4; ++i)
            #pragma unroll
            for (int j = 0; j < NV * 4; ++j)
                acc[i][j] = fmaf(ah[i], b1r[j], fmaf(ag[i], b2r[j], acc[i][j]));
    }

    float bs[NV * 4];
    #pragma unroll
    for (int g = 0; g < NV; ++g)
        #pragma unroll
        for (int j = 0; j < 4; ++j)
            bs[4*g+j] = B1[c0 + g*32 + j] + B2[c0 + g*32 + j];

    #pragma unroll
    for (int i = 0; i < 4; ++i) {
        int m = m0 + mrow + i;
        if (m >= n) continue;
        #pragma unroll
        for (int g = 0; g < NV; ++g) {
            float4 r;
            r.x = acc[i][4*g+0] + bs[4*g+0];
            r.y = acc[i][4*g+1] + bs[4*g+1];
            r.z = acc[i][4*g+2] + bs[4*g+2];
            r.w = acc[i][4*g+3] + bs[4*g+3];
            if (RELU) {
                r.x = fmaxf(r.x, 0.f); r.y = fmaxf(r.y, 0.f);
                r.z = fmaxf(r.z, 0.f); r.w = fmaxf(r.w, 0.f);
            }
            reinterpret_cast<float4*>(OUT)[(size_t)m * (FOUT / 4) + ((c0 + g*32) >> 2)] = r;
        }
    }
}

// =====================================================================
// SpMM scatter: AGG[dst,:] += val * H[src,:]^2   (warp/edge, red.v4)
// =====================================================================
__global__ __launch_bounds__(256)
void spmm_kernel(const int* __restrict__ src, const int* __restrict__ dst,
                 const float* __restrict__ val, const float* __restrict__ Hm,
                 float* __restrict__ AGG, int E)
{
    int gw = (int)((blockIdx.x * 256u + threadIdx.x) >> 5);
    int lane = threadIdx.x & 31;
    if (gw >= E) return;
    int s = src[gw];
    int d = dst[gw];
    float v = val[gw];
    float4 h = reinterpret_cast<const float4*>(Hm)[(size_t)s * 32 + lane];
    float4 r;
    r.x = h.x * h.x * v;
    r.y = h.y * h.y * v;
    r.z = h.z * h.z * v;
    r.w = h.w * h.w * v;
    float* p = AGG + (size_t)d * 128 + lane * 4;
    asm volatile("red.global.add.v4.f32 [%0], {%1, %2, %3, %4};"
                 :: "l"(p), "f"(r.x), "f"(r.y), "f"(r.z), "f"(r.w) : "memory");
}

__global__ void zero_kernel(float4* __restrict__ p, int n4)
{
    int i = blockIdx.x * blockDim.x + threadIdx.x;
    int stride = gridDim.x * blockDim.x;
    float4 z = make_float4(0.f, 0.f, 0.f, 0.f);
    for (; i < n4; i += stride) p[i] = z;
}

// =====================================================================
extern "C" void kernel_launch(void* const* d_in, const int* in_sizes, int n_in,
                              void* d_out, int out_size)
{
    const float* x     = (const float*)d_in[0];
    const int*   esrc  = (const int*)  d_in[1];
    const int*   edst  = (const int*)  d_in[2];
    const float* eval_ = (const float*)d_in[3];
    const float* pw0   = (const float*)d_in[4];
    const float* pb0   = (const float*)d_in[5];
    const float* f1w0  = (const float*)d_in[6];
    const float* f1b0  = (const float*)d_in[7];
    const float* f2w0  = (const float*)d_in[8];
    const float* f2b0  = (const float*)d_in[9];
    const float* pw1   = (const float*)d_in[10];
    const float* pb1   = (const float*)d_in[11];
    const float* f1w1  = (const float*)d_in[12];
    const float* f1b1  = (const float*)d_in[13];
    const float* f2w1  = (const float*)d_in[14];
    const float* f2b1  = (const float*)d_in[15];
    float* out = (float*)d_out;

    int n = in_sizes[0] / KD;
    int E = in_sizes[1];

    float *hP, *aP, *oP;
    cudaGetSymbolAddress((void**)&hP, g_h);
    cudaGetSymbolAddress((void**)&aP, g_agg);
    cudaGetSymbolAddress((void**)&oP, g_o0);

    const int POOL_SMEM  = (KD * 68 + KD * 132 + 64) * 4;
    const int FC128_SMEM = (2 * KD * 68 + 2 * KD * 132) * 4;
    const int FC64_SMEM  = (2 * KD * 68 + 2 * KD * 68) * 4;
    cudaFuncSetAttribute(pool_gemm,          cudaFuncAttributeMaxDynamicSharedMemorySize, POOL_SMEM);
    cudaFuncSetAttribute(fc_gemm<128, true>, cudaFuncAttributeMaxDynamicSharedMemorySize, FC128_SMEM);
    cudaFuncSetAttribute(fc_gemm<64, false>, cudaFuncAttributeMaxDynamicSharedMemorySize, FC64_SMEM);

    int mb = (n + 63) / 64;
    int sb = (int)(((long long)E * 32 + 255) / 256);

    // ---- layer 0 ----
    pool_gemm<<<mb, 256, POOL_SMEM>>>(x, pw0, pb0, hP, n);
    zero_kernel<<<2048, 256>>>((float4*)aP, n * 32);
    spmm_kernel<<<sb, 256>>>(esrc, edst, eval_, hP, aP, E);
    fc_gemm<128, true><<<mb, 256, FC128_SMEM>>>(hP, aP, f1w0, f2w0, f1b0, f2b0, oP, n);

    // ---- layer 1 ----
    pool_gemm<<<mb, 256, POOL_SMEM>>>(oP, pw1, pb1, hP, n);
    zero_kernel<<<2048, 256>>>((float4*)aP, n * 32);
    spmm_kernel<<<sb, 256>>>(esrc, edst, eval_, hP, aP, E);
    fc_gemm<64, false><<<mb, 256, FC64_SMEM>>>(hP, aP, f1w1, f2w1, f1b1, f2b1, out, n);
}

// round 3
// speedup vs baseline: 1.2103x; 1.0425x over previous
#include <cuda_runtime.h>
#include <math.h>

#define NMAX 50000
#define KD 128

__device__ float g_h[(size_t)NMAX * KD];
__device__ float g_agg[(size_t)NMAX * KD];
__device__ float g_o0[(size_t)NMAX * KD];

// =====================================================================
// pool GEMM + fused row L2-norm:
//   H[m,o] = relu( inv_norm[m] * (X[m,:] . W[o,:]) + B[o] )
// =====================================================================
__global__ __launch_bounds__(256, 2)
void pool_gemm(const float* __restrict__ X, const float* __restrict__ W,
               const float* __restrict__ B, float* __restrict__ H, int n)
{
    extern __shared__ float sm[];
    float* As   = sm;                 // [128 k][68 row]
    float* Ws   = As + KD * 68;       // [128 k][132 col]
    float* invn = Ws + KD * 132;      // [64]

    const int t = threadIdx.x;
    const int warp = t >> 5, lane = t & 31;
    const int m0 = blockIdx.x * 64;

    for (int i = t; i < KD * KD; i += 256) {
        int o = i >> 7, k = i & 127;
        Ws[k * 132 + o] = W[i];
    }

    #pragma unroll
    for (int i = 0; i < 8; ++i) {
        int row = warp + 8 * i;
        int m = m0 + row;
        float4 v = make_float4(0.f, 0.f, 0.f, 0.f);
        if (m < n) v = reinterpret_cast<const float4*>(X)[(size_t)m * 32 + lane];
        float s = v.x * v.x + v.y * v.y + v.z * v.z + v.w * v.w;
        #pragma unroll
        for (int off = 16; off > 0; off >>= 1)
            s += __shfl_xor_sync(0xffffffffu, s, off);
        if (lane == 0) invn[row] = 1.0f / fmaxf(sqrtf(s), 1e-12f);
        int k = lane * 4;
        As[(k + 0) * 68 + row] = v.x;
        As[(k + 1) * 68 + row] = v.y;
        As[(k + 2) * 68 + row] = v.z;
        As[(k + 3) * 68 + row] = v.w;
    }
    __syncthreads();

    const int wr = warp & 3, wc = warp >> 2;
    const int lr = lane >> 3, lc = lane & 7;
    const int mrow = wr * 16 + lr * 4;
    const int c0 = wc * 64 + lc * 4;       // strided col pair: c0, c0+32

    float acc[4][8];
    #pragma unroll
    for (int i = 0; i < 4; ++i)
        #pragma unroll
        for (int j = 0; j < 8; ++j) acc[i][j] = 0.f;

    #pragma unroll 8
    for (int k = 0; k < KD; ++k) {
        float4 av  = *reinterpret_cast<const float4*>(&As[k * 68 + mrow]);
        float4 b0v = *reinterpret_cast<const float4*>(&Ws[k * 132 + c0]);
        float4 b1v = *reinterpret_cast<const float4*>(&Ws[k * 132 + c0 + 32]);
        float a[4] = {av.x, av.y, av.z, av.w};
        float b[8] = {b0v.x, b0v.y, b0v.z, b0v.w, b1v.x, b1v.y, b1v.z, b1v.w};
        #pragma unroll
        for (int i = 0; i < 4; ++i)
            #pragma unroll
            for (int j = 0; j < 8; ++j)
                acc[i][j] = fmaf(a[i], b[j], acc[i][j]);
    }

    float bs[8];
    #pragma unroll
    for (int j = 0; j < 4; ++j) { bs[j] = B[c0 + j]; bs[j + 4] = B[c0 + 32 + j]; }

    #pragma unroll
    for (int i = 0; i < 4; ++i) {
        int m = m0 + mrow + i;
        if (m >= n) continue;
        float inv = invn[mrow + i];
        float4 r0, r1;
        r0.x = fmaxf(fmaf(acc[i][0], inv, bs[0]), 0.f);
        r0.y = fmaxf(fmaf(acc[i][1], inv, bs[1]), 0.f);
        r0.z = fmaxf(fmaf(acc[i][2], inv, bs[2]), 0.f);
        r0.w = fmaxf(fmaf(acc[i][3], inv, bs[3]), 0.f);
        r1.x = fmaxf(fmaf(acc[i][4], inv, bs[4]), 0.f);
        r1.y = fmaxf(fmaf(acc[i][5], inv, bs[5]), 0.f);
        r1.z = fmaxf(fmaf(acc[i][6], inv, bs[6]), 0.f);
        r1.w = fmaxf(fmaf(acc[i][7], inv, bs[7]), 0.f);
        reinterpret_cast<float4*>(H)[(size_t)m * 32 + (c0 >> 2)]     = r0;
        reinterpret_cast<float4*>(H)[(size_t)m * 32 + (c0 >> 2) + 8] = r1;
    }
}

// =====================================================================
// fused fc, TWO-PASS (halved smem -> 2-3 CTAs/SM):
//   pass 0: acc += H . W1^T      pass 1: acc += sqrt(G) . W2^T
//   OUT = act(acc + B1 + B2)
// =====================================================================
template <int FOUT, bool RELU, int MINB>
__global__ __launch_bounds__(256, MINB)
void fc_gemm(const float* __restrict__ Hin, const float* __restrict__ G,
             const float* __restrict__ W1, const float* __restrict__ W2,
             const float* __restrict__ B1, const float* __restrict__ B2,
             float* __restrict__ OUT, int n)
{
    constexpr int WP = FOUT + 4;
    constexpr int NV = FOUT / 64;          // 2 for 128, 1 for 64
    extern __shared__ float sm[];
    float* As = sm;                        // [128 k][68 row]
    float* Ws = As + KD * 68;              // [128 k][WP col]

    const int t = threadIdx.x;
    const int warp = t >> 5, lane = t & 31;
    const int m0 = blockIdx.x * 64;

    const int wr = warp & 3, wc = warp >> 2;
    const int lr = lane >> 3, lc = lane & 7;
    const int mrow = wr * 16 + lr * 4;
    const int c0 = wc * (FOUT / 2) + lc * 4;

    float acc[4][NV * 4];
    #pragma unroll
    for (int i = 0; i < 4; ++i)
        #pragma unroll
        for (int j = 0; j < NV * 4; ++j) acc[i][j] = 0.f;

    #pragma unroll
    for (int pass = 0; pass < 2; ++pass) {
        const float* Ain = pass ? G : Hin;
        const float* Wm  = pass ? W2 : W1;

        // stage W
        for (int i = t; i < FOUT * KD; i += 256) {
            int o = i >> 7, k = i & 127;
            Ws[k * WP + o] = Wm[i];
        }
        // stage A (sqrt on pass 1)
        #pragma unroll
        for (int i = 0; i < 8; ++i) {
            int row = warp + 8 * i;
            int m = m0 + row;
            float4 v = make_float4(0.f, 0.f, 0.f, 0.f);
            if (m < n) v = reinterpret_cast<const float4*>(Ain)[(size_t)m * 32 + lane];
            if (pass) {
                v.x = sqrtf(v.x); v.y = sqrtf(v.y);
                v.z = sqrtf(v.z); v.w = sqrtf(v.w);
            }
            int k = lane * 4;
            As[(k + 0) * 68 + row] = v.x;
            As[(k + 1) * 68 + row] = v.y;
            As[(k + 2) * 68 + row] = v.z;
            As[(k + 3) * 68 + row] = v.w;
        }
        __syncthreads();

        #pragma unroll 8
        for (int k = 0; k < KD; ++k) {
            float4 av = *reinterpret_cast<const float4*>(&As[k * 68 + mrow]);
            float a[4] = {av.x, av.y, av.z, av.w};
            float br[NV * 4];
            #pragma unroll
            for (int g = 0; g < NV; ++g) {
                float4 wv = *reinterpret_cast<const float4*>(&Ws[k * WP + c0 + g * 32]);
                br[4*g+0] = wv.x; br[4*g+1] = wv.y;
                br[4*g+2] = wv.z; br[4*g+3] = wv.w;
            }
            #pragma unroll
            for (int i = 0; i < 4; ++i)
                #pragma unroll
                for (int j = 0; j < NV * 4; ++j)
                    acc[i][j] = fmaf(a[i], br[j], acc[i][j]);
        }
        if (pass == 0) __syncthreads();   // protect smem before overwrite
    }

    float bs[NV * 4];
    #pragma unroll
    for (int g = 0; g < NV; ++g)
        #pragma unroll
        for (int j = 0; j < 4; ++j)
            bs[4*g+j] = B1[c0 + g*32 + j] + B2[c0 + g*32 + j];

    #pragma unroll
    for (int i = 0; i < 4; ++i) {
        int m = m0 + mrow + i;
        if (m >= n) continue;
        #pragma unroll
        for (int g = 0; g < NV; ++g) {
            float4 r;
            r.x = acc[i][4*g+0] + bs[4*g+0];
            r.y = acc[i][4*g+1] + bs[4*g+1];
            r.z = acc[i][4*g+2] + bs[4*g+2];
            r.w = acc[i][4*g+3] + bs[4*g+3];
            if (RELU) {
                r.x = fmaxf(r.x, 0.f); r.y = fmaxf(r.y, 0.f);
                r.z = fmaxf(r.z, 0.f); r.w = fmaxf(r.w, 0.f);
            }
            reinterpret_cast<float4*>(OUT)[(size_t)m * (FOUT / 4) + ((c0 + g*32) >> 2)] = r;
        }
    }
}

// =====================================================================
// SpMM scatter: AGG[dst,:] += val * H[src,:]^2   (warp/edge, red.v4)
// =====================================================================
__global__ __launch_bounds__(256)
void spmm_kernel(const int* __restrict__ src, const int* __restrict__ dst,
                 const float* __restrict__ val, const float* __restrict__ Hm,
                 float* __restrict__ AGG, int E)
{
    int gw = (int)((blockIdx.x * 256u + threadIdx.x) >> 5);
    int lane = threadIdx.x & 31;
    if (gw >= E) return;
    int s = src[gw];
    int d = dst[gw];
    float v = val[gw];
    float4 h = reinterpret_cast<const float4*>(Hm)[(size_t)s * 32 + lane];
    float4 r;
    r.x = h.x * h.x * v;
    r.y = h.y * h.y * v;
    r.z = h.z * h.z * v;
    r.w = h.w * h.w * v;
    float* p = AGG + (size_t)d * 128 + lane * 4;
    asm volatile("red.global.add.v4.f32 [%0], {%1, %2, %3, %4};"
                 :: "l"(p), "f"(r.x), "f"(r.y), "f"(r.z), "f"(r.w) : "memory");
}

__global__ void zero_kernel(float4* __restrict__ p, int n4)
{
    int i = blockIdx.x * blockDim.x + threadIdx.x;
    int stride = gridDim.x * blockDim.x;
    float4 z = make_float4(0.f, 0.f, 0.f, 0.f);
    for (; i < n4; i += stride) p[i] = z;
}

// =====================================================================
extern "C" void kernel_launch(void* const* d_in, const int* in_sizes, int n_in,
                              void* d_out, int out_size)
{
    const float* x     = (const float*)d_in[0];
    const int*   esrc  = (const int*)  d_in[1];
    const int*   edst  = (const int*)  d_in[2];
    const float* eval_ = (const float*)d_in[3];
    const float* pw0   = (const float*)d_in[4];
    const float* pb0   = (const float*)d_in[5];
    const float* f1w0  = (const float*)d_in[6];
    const float* f1b0  = (const float*)d_in[7];
    const float* f2w0  = (const float*)d_in[8];
    const float* f2b0  = (const float*)d_in[9];
    const float* pw1   = (const float*)d_in[10];
    const float* pb1   = (const float*)d_in[11];
    const float* f1w1  = (const float*)d_in[12];
    const float* f1b1  = (const float*)d_in[13];
    const float* f2w1  = (const float*)d_in[14];
    const float* f2b1  = (const float*)d_in[15];
    float* out = (float*)d_out;

    int n = in_sizes[0] / KD;
    int E = in_sizes[1];

    float *hP, *aP, *oP;
    cudaGetSymbolAddress((void**)&hP, g_h);
    cudaGetSymbolAddress((void**)&aP, g_agg);
    cudaGetSymbolAddress((void**)&oP, g_o0);

    const int POOL_SMEM  = (KD * 68 + KD * 132 + 64) * 4;   // 102,912 B
    const int FC128_SMEM = (KD * 68 + KD * 132) * 4;        // 102,400 B
    const int FC64_SMEM  = (KD * 68 + KD * 68) * 4;         //  69,632 B
    cudaFuncSetAttribute(pool_gemm, cudaFuncAttributeMaxDynamicSharedMemorySize, POOL_SMEM);
    cudaFuncSetAttribute((const void*)fc_gemm<128, true, 2>,
                         cudaFuncAttributeMaxDynamicSharedMemorySize, FC128_SMEM);
    cudaFuncSetAttribute((const void*)fc_gemm<64, false, 3>,
                         cudaFuncAttributeMaxDynamicSharedMemorySize, FC64_SMEM);

    int mb = (n + 63) / 64;
    int sb = (int)(((long long)E * 32 + 255) / 256);

    // ---- layer 0 ----
    pool_gemm<<<mb, 256, POOL_SMEM>>>(x, pw0, pb0, hP, n);
    zero_kernel<<<2048, 256>>>((float4*)aP, n * 32);
    spmm_kernel<<<sb, 256>>>(esrc, edst, eval_, hP, aP, E);
    fc_gemm<128, true, 2><<<mb, 256, FC128_SMEM>>>(hP, aP, f1w0, f2w0, f1b0, f2b0, oP, n);

    // ---- layer 1 ----
    pool_gemm<<<mb, 256, POOL_SMEM>>>(oP, pw1, pb1, hP, n);
    zero_kernel<<<2048, 256>>>((float4*)aP, n * 32);
    spmm_kernel<<<sb, 256>>>(esrc, edst, eval_, hP, aP, E);
    fc_gemm<64, false, 3><<<mb, 256, FC64_SMEM>>>(hP, aP, f1w1, f2w1, f1b1, f2b1, out, n);
}